// round 1
// baseline (speedup 1.0000x reference)
#include <cuda_runtime.h>

// ---------------------------------------------------------------------------
// System1LoRA: 10 sequential steps of
//   h_n = h + 0.01*noise_t
//   op_logits = h_n @ W_op + b_op        -> argmax -> all==0 ? set allstop
//   x_logits  = h_n @ W_x  + b_x         -> argmax (first-index) -> ptr
//   borrowed  = s2a[b, ptr, :]
//   h_new     = [h_n, borrowed] @ W_res + b_res
//   h         = done ? h : h_new ;  done |= allstop
// All fp32 (argmax stability), inner loops use packed fma.rn.f32x2 (sm_10x).
// ---------------------------------------------------------------------------

#define B 64
#define S 4096
#define H 1024
#define NOPS 8
#define TSTEPS 10

#define TBx 16    // batch tile for GEMMs
#define TSx 128   // output-column tile
#define KC  16    // k-chunk
#define NSPLIT 4
#define KSPLIT 512  // 2048 / NSPLIT

typedef unsigned long long ull;

__device__ float g_h[B * H];
__device__ float g_part[NSPLIT * B * H];
__device__ ull   g_xkey[B];
__device__ int   g_done;
__device__ int   g_allstop;

// ---- packed f32x2 helpers --------------------------------------------------
__device__ __forceinline__ ull pack2f(float lo, float hi) {
    ull r;
    asm("mov.b64 %0, {%1, %2};" : "=l"(r)
        : "r"(__float_as_uint(lo)), "r"(__float_as_uint(hi)));
    return r;
}
__device__ __forceinline__ float2 unpack2f(ull v) {
    unsigned lo, hi;
    asm("mov.b64 {%0, %1}, %2;" : "=r"(lo), "=r"(hi) : "l"(v));
    return make_float2(__uint_as_float(lo), __uint_as_float(hi));
}
__device__ __forceinline__ void ffma2(ull& acc, ull a, ull b) {
    asm("fma.rn.f32x2 %0, %1, %2, %0;" : "+l"(acc) : "l"(a), "l"(b));
}
// order-preserving float -> uint32 (for 64-bit argmax keys)
__device__ __forceinline__ unsigned ordf(float f) {
    unsigned u = __float_as_uint(f);
    return (u & 0x80000000u) ? ~u : (u | 0x80000000u);
}

// ---- init ------------------------------------------------------------------
__global__ void k_begin() {
    int i = blockIdx.x * blockDim.x + threadIdx.x;
    if (i < B * H) g_h[i] = 0.0f;
    if (i < B) g_xkey[i] = 0ull;
    if (i == 0) { g_done = 0; g_allstop = 1; }
}

// ---- op logits + "all stop" flag -------------------------------------------
__global__ __launch_bounds__(256) void k_op(const float* __restrict__ noise_t,
                                            const float* __restrict__ Wop,
                                            const float* __restrict__ bop) {
    int b = blockIdx.x, tid = threadIdx.x;
    float p[NOPS];
#pragma unroll
    for (int o = 0; o < NOPS; o++) p[o] = 0.0f;
    const float* hb = g_h + b * H;
    const float* nb = noise_t + b * H;
    for (int h = tid; h < H; h += 256) {
        float a = hb[h] + 0.01f * nb[h];
        const float* w = Wop + h * NOPS;
#pragma unroll
        for (int o = 0; o < NOPS; o++) p[o] = fmaf(a, w[o], p[o]);
    }
    __shared__ float sred[NOPS][256];
#pragma unroll
    for (int o = 0; o < NOPS; o++) sred[o][tid] = p[o];
    __syncthreads();
    for (int st = 128; st > 0; st >>= 1) {
        if (tid < st) {
#pragma unroll
            for (int o = 0; o < NOPS; o++) sred[o][tid] += sred[o][tid + st];
        }
        __syncthreads();
    }
    if (tid == 0) {
        float best = sred[0][0] + bop[0];
        int bi = 0;
#pragma unroll
        for (int o = 1; o < NOPS; o++) {
            float v = sred[o][0] + bop[o];
            if (v > best) { best = v; bi = o; }   // strictly-greater => first index
        }
        if (bi != 0) g_allstop = 0;               // OP_STOP_IDX == 0
    }
}

// ---- x_logits GEMM fused with per-row argmax --------------------------------
// grid (S/TSx, B/TBx), 256 threads; thread grid 8(b)x32(s), microtile 2x4.
__global__ __launch_bounds__(256) void k_x(const float* __restrict__ noise_t,
                                           const float* __restrict__ Wx,
                                           const float* __restrict__ bx) {
    __shared__ float sh_a[KC][TBx + 1];
    __shared__ __align__(16) float sh_w[KC][TSx];
    int tid = threadIdx.x;
    int tb = tid >> 5, ts = tid & 31;
    int s0 = blockIdx.x * TSx;
    int b0 = blockIdx.y * TBx;
    int lb = tid >> 4, lk = tid & 15;

    ull acc0 = pack2f(0.f, 0.f), acc1 = acc0, acc2 = acc0, acc3 = acc0;

    for (int k0 = 0; k0 < H; k0 += KC) {
        {
            int gi = (b0 + lb) * H + k0 + lk;
            sh_a[lk][lb] = g_h[gi] + 0.01f * noise_t[gi];
        }
#pragma unroll
        for (int r = 0; r < 2; r++) {
            int e = r * 256 + tid;       // float4 index over KC x (TSx/4)
            int k = e >> 5, c4 = e & 31;
            *(float4*)&sh_w[k][c4 * 4] =
                *(const float4*)&Wx[(size_t)(k0 + k) * S + s0 + c4 * 4];
        }
        __syncthreads();
#pragma unroll
        for (int k = 0; k < KC; k++) {
            float a0 = sh_a[k][2 * tb], a1 = sh_a[k][2 * tb + 1];
            ull A0 = pack2f(a0, a0), A1 = pack2f(a1, a1);
            const ulonglong2 wv = *(const ulonglong2*)&sh_w[k][ts * 4];
            ffma2(acc0, A0, wv.x); ffma2(acc1, A0, wv.y);
            ffma2(acc2, A1, wv.x); ffma2(acc3, A1, wv.y);
        }
        __syncthreads();
    }

    // unpack + argmax (first-index tiebreak)
    float v[2][4];
    float2 t;
    t = unpack2f(acc0); v[0][0] = t.x; v[0][1] = t.y;
    t = unpack2f(acc1); v[0][2] = t.x; v[0][3] = t.y;
    t = unpack2f(acc2); v[1][0] = t.x; v[1][1] = t.y;
    t = unpack2f(acc3); v[1][2] = t.x; v[1][3] = t.y;
    int sbase = s0 + ts * 4;
    float bxv[4];
#pragma unroll
    for (int j = 0; j < 4; j++) bxv[j] = bx[sbase + j];

#pragma unroll
    for (int r = 0; r < 2; r++) {
        float best = v[r][0] + bxv[0];
        int bi = sbase;
#pragma unroll
        for (int j = 1; j < 4; j++) {
            float val = v[r][j] + bxv[j];
            if (val > best) { best = val; bi = sbase + j; }
        }
#pragma unroll
        for (int off = 16; off > 0; off >>= 1) {
            float ov = __shfl_down_sync(0xffffffffu, best, off);
            int   oi = __shfl_down_sync(0xffffffffu, bi, off);
            if (ov > best || (ov == best && oi < bi)) { best = ov; bi = oi; }
        }
        if (ts == 0) {
            ull key = ((ull)ordf(best) << 32) | (ull)(0xFFFFFFFFu - (unsigned)bi);
            atomicMax(&g_xkey[b0 + 2 * tb + r], key);
        }
    }
}

// ---- residual GEMM [64,2048]@[2048,1024], split-K=4, deterministic ----------
// grid (H/TSx, B/TBx, NSPLIT), 256 threads; concat operand built on the fly.
__global__ __launch_bounds__(256) void k_res(const float* __restrict__ noise_t,
                                             const float* __restrict__ Wres,
                                             const float* __restrict__ s2a) {
    __shared__ float sh_a[KC][TBx + 1];
    __shared__ __align__(16) float sh_w[KC][TSx];
    int tid = threadIdx.x;
    int tb = tid >> 5, ts = tid & 31;
    int j0 = blockIdx.x * TSx;
    int b0 = blockIdx.y * TBx;
    int kbeg = blockIdx.z * KSPLIT;
    int lb = tid >> 4, lk = tid & 15;
    int bg = b0 + lb;

    ull acc0 = pack2f(0.f, 0.f), acc1 = acc0, acc2 = acc0, acc3 = acc0;

    for (int kc = 0; kc < KSPLIT; kc += KC) {
        int kg = kbeg + kc + lk;
        float aval;
        if (kg < H) {
            int gi = bg * H + kg;
            aval = g_h[gi] + 0.01f * noise_t[gi];
        } else {
            unsigned ptr = 0xFFFFFFFFu - (unsigned)(g_xkey[bg]);
            if (ptr > (unsigned)(S - 1)) ptr = S - 1;
            aval = s2a[((size_t)bg * S + ptr) * H + (kg - H)];
        }
        sh_a[lk][lb] = aval;
#pragma unroll
        for (int r = 0; r < 2; r++) {
            int e = r * 256 + tid;
            int k = e >> 5, c4 = e & 31;
            *(float4*)&sh_w[k][c4 * 4] =
                *(const float4*)&Wres[(size_t)(kbeg + kc + k) * H + j0 + c4 * 4];
        }
        __syncthreads();
#pragma unroll
        for (int k = 0; k < KC; k++) {
            float a0 = sh_a[k][2 * tb], a1 = sh_a[k][2 * tb + 1];
            ull A0 = pack2f(a0, a0), A1 = pack2f(a1, a1);
            const ulonglong2 wv = *(const ulonglong2*)&sh_w[k][ts * 4];
            ffma2(acc0, A0, wv.x); ffma2(acc1, A0, wv.y);
            ffma2(acc2, A1, wv.x); ffma2(acc3, A1, wv.y);
        }
        __syncthreads();
    }

    int ks = blockIdx.z;
    float* out0 = &g_part[((size_t)ks * B + (b0 + 2 * tb)) * H + j0 + ts * 4];
    float* out1 = &g_part[((size_t)ks * B + (b0 + 2 * tb + 1)) * H + j0 + ts * 4];
    float2 p;
    p = unpack2f(acc0); out0[0] = p.x; out0[1] = p.y;
    p = unpack2f(acc1); out0[2] = p.x; out0[3] = p.y;
    p = unpack2f(acc2); out1[0] = p.x; out1[1] = p.y;
    p = unpack2f(acc3); out1[2] = p.x; out1[3] = p.y;
}

// ---- combine split-K partials, apply bias + freeze --------------------------
__global__ void k_combine(const float* __restrict__ bres) {
    int i = blockIdx.x * blockDim.x + threadIdx.x;   // B*H threads
    if (g_done) return;                               // frozen: keep old h
    int j = i & (H - 1);
    float v = g_part[i] + g_part[B * H + i] + g_part[2 * B * H + i] +
              g_part[3 * B * H + i] + bres[j];
    g_h[i] = v;
}

// ---- end-of-step bookkeeping ------------------------------------------------
__global__ void k_fin() {
    int t = threadIdx.x;
    if (t < B) g_xkey[t] = 0ull;
    if (t == 0) { g_done |= g_allstop; g_allstop = 1; }
}

// ---- write output -----------------------------------------------------------
__global__ void k_out(float* __restrict__ out) {
    int i = blockIdx.x * blockDim.x + threadIdx.x;
    out[i] = g_h[i];
}

// ---------------------------------------------------------------------------
extern "C" void kernel_launch(void* const* d_in, const int* in_sizes, int n_in,
                              void* d_out, int out_size) {
    const float* s2a   = (const float*)d_in[0];  // [B,S,H]
    const float* Wres  = (const float*)d_in[1];  // [2H,H]
    const float* bres  = (const float*)d_in[2];  // [H]
    const float* Wop   = (const float*)d_in[3];  // [H,NOPS]
    const float* bop   = (const float*)d_in[4];  // [NOPS]
    const float* Wx    = (const float*)d_in[5];  // [H,S]
    const float* bx    = (const float*)d_in[6];  // [S]
    const float* noise = (const float*)d_in[7];  // [T,B,H]
    float* out = (float*)d_out;

    k_begin<<<(B * H + 255) / 256, 256>>>();
    for (int t = 0; t < TSTEPS; t++) {
        const float* nt = noise + (size_t)t * B * H;
        k_op<<<B, 256>>>(nt, Wop, bop);
        k_x<<<dim3(S / TSx, B / TBx), 256>>>(nt, Wx, bx);
        k_res<<<dim3(H / TSx, B / TBx, NSPLIT), 256>>>(nt, Wres, s2a);
        k_combine<<<(B * H) / 256, 256>>>(bres);
        k_fin<<<1, 64>>>();
    }
    k_out<<<(B * H) / 256, 256>>>(out);
}

// round 2
// speedup vs baseline: 1.6767x; 1.6767x over previous
#include <cuda_runtime.h>

// ---------------------------------------------------------------------------
// System1LoRA — round 2: latency-tolerant fp32 SIMT GEMMs (f32x2 FMA),
// k-major activation staging, fused op-head, split-K + deterministic combine.
// ---------------------------------------------------------------------------

#define B 64
#define S 4096
#define H 1024
#define NOPS 8
#define TSTEPS 10

#define XSPLIT 4     // split-K for x GEMM   (Kslice = 256)
#define RSPLIT 16    // split-K for res GEMM (Kslice = 128)
#define KC 64        // shared-memory k-chunk

typedef unsigned long long ull;

__device__ float g_h[B * H];          // persistent hidden state, m-major
__device__ float g_aT[2 * H * B];     // activations k-major: [0..H) h_nT, [H..2H) borrowedT
__device__ float g_px[XSPLIT * B * S];  // x-logit partials
__device__ float g_pr[RSPLIT * B * H];  // res partials
__device__ int   g_ptr[B];
__device__ int   g_stop[TSTEPS];      // 1 if all op_idx==0 at step t

// ---- packed f32x2 helpers --------------------------------------------------
__device__ __forceinline__ ull pack2f(float lo, float hi) {
    ull r;
    asm("mov.b64 %0, {%1, %2};" : "=l"(r)
        : "r"(__float_as_uint(lo)), "r"(__float_as_uint(hi)));
    return r;
}
__device__ __forceinline__ float2 unpack2f(ull v) {
    unsigned lo, hi;
    asm("mov.b64 {%0, %1}, %2;" : "=r"(lo), "=r"(hi) : "l"(v));
    return make_float2(__uint_as_float(lo), __uint_as_float(hi));
}
__device__ __forceinline__ void ffma2(ull& acc, ull a, ull b) {
    asm("fma.rn.f32x2 %0, %1, %2, %0;" : "+l"(acc) : "l"(a), "l"(b));
}

// ---- init ------------------------------------------------------------------
__global__ void k_begin() {
    int i = blockIdx.x * blockDim.x + threadIdx.x;
    if (i < B * H) g_h[i] = 0.0f;
    if (i < TSTEPS) g_stop[i] = 1;
}

// ---- per-step prep: h_n, its transpose, op logits + allstop -----------------
// grid = B blocks (one batch row), 256 threads; each thread owns 4 consecutive j.
__global__ __launch_bounds__(256) void k_prep(const float* __restrict__ noise_t,
                                              const float* __restrict__ Wop,
                                              const float* __restrict__ bop,
                                              int t) {
    int b = blockIdx.x, tid = threadIdx.x;
    int j0 = 4 * tid;
    const float4 hv = *(const float4*)&g_h[b * H + j0];
    const float4 nv = *(const float4*)&noise_t[b * H + j0];
    float hn[4] = { fmaf(0.01f, nv.x, hv.x), fmaf(0.01f, nv.y, hv.y),
                    fmaf(0.01f, nv.z, hv.z), fmaf(0.01f, nv.w, hv.w) };
#pragma unroll
    for (int i = 0; i < 4; i++) g_aT[(j0 + i) * B + b] = hn[i];

    float p[NOPS];
#pragma unroll
    for (int o = 0; o < NOPS; o++) p[o] = 0.0f;
#pragma unroll
    for (int i = 0; i < 4; i++) {
        const float4 w0 = *(const float4*)&Wop[(j0 + i) * NOPS];
        const float4 w1 = *(const float4*)&Wop[(j0 + i) * NOPS + 4];
        p[0] = fmaf(hn[i], w0.x, p[0]); p[1] = fmaf(hn[i], w0.y, p[1]);
        p[2] = fmaf(hn[i], w0.z, p[2]); p[3] = fmaf(hn[i], w0.w, p[3]);
        p[4] = fmaf(hn[i], w1.x, p[4]); p[5] = fmaf(hn[i], w1.y, p[5]);
        p[6] = fmaf(hn[i], w1.z, p[6]); p[7] = fmaf(hn[i], w1.w, p[7]);
    }
    __shared__ float sred[NOPS][256];
#pragma unroll
    for (int o = 0; o < NOPS; o++) sred[o][tid] = p[o];
    __syncthreads();
    for (int st = 128; st > 0; st >>= 1) {
        if (tid < st) {
#pragma unroll
            for (int o = 0; o < NOPS; o++) sred[o][tid] += sred[o][tid + st];
        }
        __syncthreads();
    }
    if (tid == 0) {
        float best = sred[0][0] + bop[0];
        int bi = 0;
#pragma unroll
        for (int o = 1; o < NOPS; o++) {
            float v = sred[o][0] + bop[o];
            if (v > best) { best = v; bi = o; }      // first-index tiebreak
        }
        if (bi != 0) g_stop[t] = 0;                  // OP_STOP_IDX == 0
    }
}

// ---- x GEMM: [64,1024] @ [1024,4096], CTA tile M64 x N128, split-K=4 --------
// 256 threads, thread grid 16(m-groups of 4) x 16(n-groups of 8), microtile 4x8.
__global__ __launch_bounds__(256) void k_x(const float* __restrict__ Wx) {
    __shared__ float sh_a[KC][B];      // 16 KB
    __shared__ float sh_w[KC][128];    // 32 KB
    int tid = threadIdx.x;
    int tm = tid >> 4, tn = tid & 15;
    int s0 = blockIdx.x * 128;
    int kbeg = blockIdx.y * (H / XSPLIT);

    ull acc[4][4];
#pragma unroll
    for (int i = 0; i < 4; i++)
#pragma unroll
        for (int j = 0; j < 4; j++) acc[i][j] = 0ull;

#pragma unroll
    for (int kc = 0; kc < H / XSPLIT; kc += KC) {
#pragma unroll
        for (int r = 0; r < 4; r++) {               // A chunk: [64][16 f4]
            int e = r * 256 + tid;
            int k = e >> 4, c = e & 15;
            *(float4*)&sh_a[k][4 * c] =
                *(const float4*)&g_aT[(kbeg + kc + k) * B + 4 * c];
        }
#pragma unroll
        for (int r = 0; r < 8; r++) {               // W chunk: [64][32 f4]
            int e = r * 256 + tid;
            int k = e >> 5, c = e & 31;
            *(float4*)&sh_w[k][4 * c] =
                *(const float4*)&Wx[(size_t)(kbeg + kc + k) * S + s0 + 4 * c];
        }
        __syncthreads();
#pragma unroll 8
        for (int k = 0; k < KC; k++) {
            float4 av = *(float4*)&sh_a[k][4 * tm];
            ull A0 = pack2f(av.x, av.x), A1 = pack2f(av.y, av.y);
            ull A2 = pack2f(av.z, av.z), A3 = pack2f(av.w, av.w);
            ulonglong2 w0 = *(ulonglong2*)&sh_w[k][8 * tn];
            ulonglong2 w1 = *(ulonglong2*)&sh_w[k][8 * tn + 4];
            ffma2(acc[0][0], A0, w0.x); ffma2(acc[0][1], A0, w0.y);
            ffma2(acc[0][2], A0, w1.x); ffma2(acc[0][3], A0, w1.y);
            ffma2(acc[1][0], A1, w0.x); ffma2(acc[1][1], A1, w0.y);
            ffma2(acc[1][2], A1, w1.x); ffma2(acc[1][3], A1, w1.y);
            ffma2(acc[2][0], A2, w0.x); ffma2(acc[2][1], A2, w0.y);
            ffma2(acc[2][2], A2, w1.x); ffma2(acc[2][3], A2, w1.y);
            ffma2(acc[3][0], A3, w0.x); ffma2(acc[3][1], A3, w0.y);
            ffma2(acc[3][2], A3, w1.x); ffma2(acc[3][3], A3, w1.y);
        }
        __syncthreads();
    }

    int ks = blockIdx.y;
#pragma unroll
    for (int i = 0; i < 4; i++) {
        float* o = &g_px[((size_t)ks * B + 4 * tm + i) * S + s0 + 8 * tn];
        float2 p0 = unpack2f(acc[i][0]), p1 = unpack2f(acc[i][1]);
        *(float4*)o = make_float4(p0.x, p0.y, p1.x, p1.y);
        p0 = unpack2f(acc[i][2]); p1 = unpack2f(acc[i][3]);
        *(float4*)(o + 4) = make_float4(p0.x, p0.y, p1.x, p1.y);
    }
}

// ---- combine x partials + bias, argmax (first-index), gather borrowedT ------
__global__ __launch_bounds__(256) void k_comb(const float* __restrict__ bx,
                                              const float* __restrict__ s2a) {
    int b = blockIdx.x, tid = threadIdx.x;
    float best = -3.4e38f;
    int bi = 0;
    for (int s = tid; s < S; s += 256) {
        size_t base = (size_t)b * S + s;
        float v = g_px[base] + g_px[(size_t)B * S + base] +
                  g_px[2 * (size_t)B * S + base] + g_px[3 * (size_t)B * S + base] +
                  bx[s];
        if (v > best) { best = v; bi = s; }          // s ascending -> first index
    }
    __shared__ float sv[256];
    __shared__ int   si[256];
    __shared__ int   sptr;
    sv[tid] = best; si[tid] = bi;
    __syncthreads();
    for (int st = 128; st > 0; st >>= 1) {
        if (tid < st) {
            float ov = sv[tid + st]; int oi = si[tid + st];
            if (ov > sv[tid] || (ov == sv[tid] && oi < si[tid])) {
                sv[tid] = ov; si[tid] = oi;
            }
        }
        __syncthreads();
    }
    if (tid == 0) {
        int p = si[0];
        if (p > S - 1) p = S - 1;
        g_ptr[b] = p;
        sptr = p;
    }
    __syncthreads();
    int ptr = sptr;
    const float* src = &s2a[((size_t)b * S + ptr) * H];
    int j = 4 * tid;
    float4 v = *(const float4*)&src[j];
    g_aT[(H + j) * B + b]     = v.x;
    g_aT[(H + j + 1) * B + b] = v.y;
    g_aT[(H + j + 2) * B + b] = v.z;
    g_aT[(H + j + 3) * B + b] = v.w;
}

// ---- res GEMM: [64,2048] @ [2048,1024], CTA tile M64 x N128, split-K=16 -----
__global__ __launch_bounds__(256) void k_res(const float* __restrict__ Wres) {
    __shared__ float sh_a[KC][B];
    __shared__ float sh_w[KC][128];
    int tid = threadIdx.x;
    int tm = tid >> 4, tn = tid & 15;
    int j0 = blockIdx.x * 128;
    int kbeg = blockIdx.y * (2 * H / RSPLIT);

    ull acc[4][4];
#pragma unroll
    for (int i = 0; i < 4; i++)
#pragma unroll
        for (int j = 0; j < 4; j++) acc[i][j] = 0ull;

#pragma unroll
    for (int kc = 0; kc < 2 * H / RSPLIT; kc += KC) {
#pragma unroll
        for (int r = 0; r < 4; r++) {
            int e = r * 256 + tid;
            int k = e >> 4, c = e & 15;
            *(float4*)&sh_a[k][4 * c] =
                *(const float4*)&g_aT[(kbeg + kc + k) * B + 4 * c];
        }
#pragma unroll
        for (int r = 0; r < 8; r++) {
            int e = r * 256 + tid;
            int k = e >> 5, c = e & 31;
            *(float4*)&sh_w[k][4 * c] =
                *(const float4*)&Wres[(size_t)(kbeg + kc + k) * H + j0 + 4 * c];
        }
        __syncthreads();
#pragma unroll 8
        for (int k = 0; k < KC; k++) {
            float4 av = *(float4*)&sh_a[k][4 * tm];
            ull A0 = pack2f(av.x, av.x), A1 = pack2f(av.y, av.y);
            ull A2 = pack2f(av.z, av.z), A3 = pack2f(av.w, av.w);
            ulonglong2 w0 = *(ulonglong2*)&sh_w[k][8 * tn];
            ulonglong2 w1 = *(ulonglong2*)&sh_w[k][8 * tn + 4];
            ffma2(acc[0][0], A0, w0.x); ffma2(acc[0][1], A0, w0.y);
            ffma2(acc[0][2], A0, w1.x); ffma2(acc[0][3], A0, w1.y);
            ffma2(acc[1][0], A1, w0.x); ffma2(acc[1][1], A1, w0.y);
            ffma2(acc[1][2], A1, w1.x); ffma2(acc[1][3], A1, w1.y);
            ffma2(acc[2][0], A2, w0.x); ffma2(acc[2][1], A2, w0.y);
            ffma2(acc[2][2], A2, w1.x); ffma2(acc[2][3], A2, w1.y);
            ffma2(acc[3][0], A3, w0.x); ffma2(acc[3][1], A3, w0.y);
            ffma2(acc[3][2], A3, w1.x); ffma2(acc[3][3], A3, w1.y);
        }
        __syncthreads();
    }

    int ks = blockIdx.y;
#pragma unroll
    for (int i = 0; i < 4; i++) {
        float* o = &g_pr[((size_t)ks * B + 4 * tm + i) * H + j0 + 8 * tn];
        float2 p0 = unpack2f(acc[i][0]), p1 = unpack2f(acc[i][1]);
        *(float4*)o = make_float4(p0.x, p0.y, p1.x, p1.y);
        p0 = unpack2f(acc[i][2]); p1 = unpack2f(acc[i][3]);
        *(float4*)(o + 4) = make_float4(p0.x, p0.y, p1.x, p1.y);
    }
}

// ---- combine res partials + bias, freeze-aware h update ---------------------
__global__ __launch_bounds__(256) void k_resfin(const float* __restrict__ bres,
                                                int t) {
    int done = 0;
    for (int u = 0; u < t; u++) done |= g_stop[u];
    if (done) return;                                // frozen: keep old h
    int idx = blockIdx.x * 256 + threadIdx.x;        // float4 index
    int e = 4 * idx;
    int j = e & (H - 1);
    float4 s = *(const float4*)&bres[j];
#pragma unroll
    for (int ks = 0; ks < RSPLIT; ks++) {
        float4 p = *(const float4*)&g_pr[(size_t)ks * B * H + e];
        s.x += p.x; s.y += p.y; s.z += p.z; s.w += p.w;
    }
    *(float4*)&g_h[e] = s;
}

// ---- output -----------------------------------------------------------------
__global__ void k_out(float* __restrict__ out) {
    int idx = blockIdx.x * 256 + threadIdx.x;
    int e = 4 * idx;
    *(float4*)&out[e] = *(const float4*)&g_h[e];
}

// ---------------------------------------------------------------------------
extern "C" void kernel_launch(void* const* d_in, const int* in_sizes, int n_in,
                              void* d_out, int out_size) {
    const float* s2a   = (const float*)d_in[0];  // [B,S,H]
    const float* Wres  = (const float*)d_in[1];  // [2H,H]
    const float* bres  = (const float*)d_in[2];  // [H]
    const float* Wop   = (const float*)d_in[3];  // [H,NOPS]
    const float* bop   = (const float*)d_in[4];  // [NOPS]
    const float* Wx    = (const float*)d_in[5];  // [H,S]
    const float* bx    = (const float*)d_in[6];  // [S]
    const float* noise = (const float*)d_in[7];  // [T,B,H]
    float* out = (float*)d_out;

    k_begin<<<(B * H + 255) / 256, 256>>>();
    for (int t = 0; t < TSTEPS; t++) {
        const float* nt = noise + (size_t)t * B * H;
        k_prep<<<B, 256>>>(nt, Wop, bop, t);
        k_x<<<dim3(S / 128, XSPLIT), 256>>>(Wx);
        k_comb<<<B, 256>>>(bx, s2a);
        k_res<<<dim3(H / 128, RSPLIT), 256>>>(Wres);
        k_resfin<<<(B * H / 4 + 255) / 256, 256>>>(bres, t);
    }
    k_out<<<(B * H / 4 + 255) / 256, 256>>>(out);
}